// round 15
// baseline (speedup 1.0000x reference)
#include <cuda_runtime.h>
#include <cstdint>

// Problem constants (fixed by the reference)
#define B_DIM 16
#define S_DIM 4096
#define H_DIM 768
#define NUM_WORDS 2048            // S/2
#define ROW_BYTES (H_DIM * 4)     // 3072 bytes per token/word row
#define NTHR 192                  // one 16B chunk per thread per row
#define W_PB 8                    // words per block
#define STAGES 6                  // cp.async pipeline depth

// Scratch: word start-token table, [B][NUM_WORDS+1].
// Word ids are contiguous 0..maxw (cumsum construction): starts[b][w] = first
// token of word w; starts[b][maxw+1] = S-1 (sentinel; token S-1 is SEP=-1).
// Entries past maxw+1 stay 0 (zero-initialized device globals; identical
// writes every call -> deterministic across graph replays). The main kernel
// monotone-repairs its 9-entry window (running max), so stale zeros become
// empty words (cnt=0 -> zero rows), matching the reference.
__device__ int g_starts[B_DIM * (NUM_WORDS + 1)];

// One warp-shuffled pass: one load per thread; prev value via __shfl_up.
__global__ void scatter_starts_kernel(const int* __restrict__ wid) {
    const int b = blockIdx.y;
    const int t = blockIdx.x * blockDim.x + threadIdx.x;   // 0..S-1
    const int* row = wid + (size_t)b * S_DIM;
    const int lane = threadIdx.x & 31;

    int w = row[t];
    int wprev = __shfl_up_sync(0xFFFFFFFFu, w, 1);
    if (lane == 0 && t > 0) wprev = row[t - 1];

    if (t >= 1 && t < S_DIM - 1) {
        if (w >= 0 && wprev != w) {
            g_starts[b * (NUM_WORDS + 1) + w] = t;
        }
    } else if (t == S_DIM - 1) {
        // wprev == row[S-2] == maxw (lane 31 of the last warp)
        g_starts[b * (NUM_WORDS + 1) + wprev + 1] = S_DIM - 1;
    }
}

// One block per (8 contiguous words, batch); grid 256 x 16 = 4096 blocks.
// The 8 words cover ONE contiguous token range [t0, tEnd). Tokens stream
// through a 6-stage per-thread cp.async smem ring; load issue is decoupled
// from the accumulate chain and continuous across word boundaries. The token
// loop is split into a bulk phase (refill always in-range: no predicates)
// and a tail phase (no cp.async at all — empty commit_groups preserve the
// wait_group/ring invariant). Every token in [t0, last] is issued exactly
// once (prologue or bulk refill), so tail consumption reads valid stages.
__global__ __launch_bounds__(NTHR, 10) void seg_mean_pipe_kernel(
    const char* __restrict__ hs,   // [B, S, H] f32 as bytes
    char*       __restrict__ out)  // [B, NUM_WORDS, H] f32 as bytes
{
    __shared__ int    sm[W_PB + 1];
    __shared__ float4 buf[STAGES][NTHR];

    const int b  = blockIdx.y;
    const int w0 = blockIdx.x * W_PB;
    const int c  = threadIdx.x;

    if (c <= W_PB) sm[c] = g_starts[b * (NUM_WORDS + 1) + w0 + c];
    __syncthreads();
    if (c == 0) {
        int run = sm[0];
#pragma unroll
        for (int i = 1; i <= W_PB; ++i) {
            run = max(run, sm[i]);
            sm[i] = run;
        }
    }
    __syncthreads();

    const int t0   = sm[0];
    const int tEnd = sm[W_PB];
    const int last = tEnd - 1;                // last in-range token index

    const char* __restrict__ base =
        hs + (size_t)b * S_DIM * ROW_BYTES + c * 16;
    char* __restrict__ ob =
        out + ((size_t)b * NUM_WORDS + w0) * ROW_BYTES + c * 16;

    // Running prefetch pointer; only dereferenced while in range.
    const char* pf = base + (long)t0 * ROW_BYTES;

    // Prologue: fill stages for tokens t0..t0+5 (skip cp.async past `last`,
    // but always commit to keep one group per stage).
#pragma unroll
    for (int j = 0; j < STAGES; ++j) {
        if (t0 + j <= last) {
            unsigned int dst =
                (unsigned int)__cvta_generic_to_shared(&buf[j][c]);
            asm volatile("cp.async.cg.shared.global [%0], [%1], 16;"
                         :: "r"(dst), "l"(pf) : "memory");
        }
        asm volatile("cp.async.commit_group;" ::: "memory");
        pf += ROW_BYTES;
    }

    int t = t0;
    int ring = 0;
#pragma unroll 1
    for (int i = 0; i < W_PB; ++i) {
        const int e   = sm[i + 1];
        const int cnt = e - t;

        float4 acc = make_float4(0.f, 0.f, 0.f, 0.f);

        // Bulk: refill token t+STAGES is guaranteed in-range.
        const int ebulk = min(e, last - STAGES + 1);
#pragma unroll 1
        while (t < ebulk) {
            asm volatile("cp.async.wait_group %0;" :: "n"(STAGES - 1)
                         : "memory");
            float4 v = buf[ring][c];
            acc.x += v.x; acc.y += v.y; acc.z += v.z; acc.w += v.w;
            unsigned int dst =
                (unsigned int)__cvta_generic_to_shared(&buf[ring][c]);
            asm volatile("cp.async.cg.shared.global [%0], [%1], 16;"
                         :: "r"(dst), "l"(pf) : "memory");
            asm volatile("cp.async.commit_group;" ::: "memory");
            pf += ROW_BYTES;
            ++t;
            if (++ring == STAGES) ring = 0;
        }
        // Tail: no more loads needed; empty groups keep the invariant.
#pragma unroll 1
        while (t < e) {
            asm volatile("cp.async.wait_group %0;" :: "n"(STAGES - 1)
                         : "memory");
            float4 v = buf[ring][c];
            acc.x += v.x; acc.y += v.y; acc.z += v.z; acc.w += v.w;
            asm volatile("cp.async.commit_group;" ::: "memory");
            ++t;
            if (++ring == STAGES) ring = 0;
        }

        const float inv = (cnt > 0) ? (1.0f / (float)cnt) : 0.0f;
        float4 r;
        r.x = acc.x * inv; r.y = acc.y * inv;
        r.z = acc.z * inv; r.w = acc.w * inv;
        __stcs((float4*)(ob + (long)i * ROW_BYTES), r);
    }
}

extern "C" void kernel_launch(void* const* d_in, const int* in_sizes, int n_in,
                              void* d_out, int out_size)
{
    const char* hs  = (const char*)d_in[0];   // hidden_states [B,S,H] f32
    const int*  wid = (const int*)d_in[1];    // word_ids [B,S] i32
    char*       out = (char*)d_out;           // [B, NUM_WORDS, H] f32

    {
        dim3 grid(S_DIM / 256, B_DIM);
        scatter_starts_kernel<<<grid, 256>>>(wid);
    }
    {
        dim3 grid(NUM_WORDS / W_PB, B_DIM);
        seg_mean_pipe_kernel<<<grid, NTHR>>>(hs, out);
    }
}

// round 16
// speedup vs baseline: 1.0535x; 1.0535x over previous
#include <cuda_runtime.h>
#include <cstdint>

// Problem constants (fixed by the reference)
#define B_DIM 16
#define S_DIM 4096
#define H_DIM 768
#define NUM_WORDS 2048            // S/2
#define ROW_BYTES (H_DIM * 4)     // 3072 bytes per token/word row
#define NTHR 192                  // one 16B chunk per thread per row
#define W_PB 8                    // words per block
#define STAGES 8                  // cp.async pipeline depth (R14-proven)

// Single fused kernel: one block per (8 contiguous words, batch).
//
// word_ids[b, 1..S-2] is non-decreasing, contiguous 0..maxw (cumsum);
// positions 0 and S-1 are -1 (CLS/SEP, dropped).
//
// Boundary discovery (cheap parallel prologue, ~1.3K cycles):
//  1) warp 0 finds t0 = lower_bound(w0) with a 32-ary ballot search
//     (3 dependent L2 rounds vs 12 for binary search);
//  2) all 192 threads scan the window row[t0 .. t0+191] (one coalesced
//     round), mark starts of words w0+1..w0+8 via neighbor compare; loop
//     windows until a token with word > w0+8 (or SEP) is seen. Unfound
//     boundaries stay S-1 (absent words -> cnt=0 -> zero rows, matches ref).
//
// Streaming mainloop (identical to round-14 best): 8-stage per-thread
// cp.async smem ring, 128B in flight/thread, issue decoupled from the
// accumulate chain and continuous across word boundaries; out-of-range
// refills use src-size=0 (zero-fill, no transaction); running prefetch
// pointer (no per-iteration 64-bit multiplies).
__global__ __launch_bounds__(NTHR) void seg_mean_fused_kernel(
    const char* __restrict__ hs,   // [B, S, H] f32 as bytes
    const int*  __restrict__ wid,  // [B, S]
    char*       __restrict__ out)  // [B, NUM_WORDS, H] f32 as bytes
{
    __shared__ int    sm[W_PB + 1];
    __shared__ int    s_done;
    __shared__ float4 buf[STAGES][NTHR];

    const int b  = blockIdx.y;
    const int w0 = blockIdx.x * W_PB;
    const int c  = threadIdx.x;

    const int* __restrict__ row = wid + (size_t)b * S_DIM;

    // Init boundary slots (S-1 = "not found" => empty word after t0).
    if (c >= 1 && c <= W_PB) sm[c] = S_DIM - 1;

    // --- 1) 32-ary ballot search for t0 = lower_bound(w0) on [1, S-1) ---
    if (c < 32) {
        int lo = 1, hi = S_DIM - 1;           // invariant: answer in [lo,hi)
        while (hi - lo > 1) {
            const int len  = hi - lo;
            const int step = (len + 31) >> 5; // ceil(len/32)
            const int p    = lo + c * step;
            const int v    = (p < hi) ? __ldg(row + p) : 0x7FFFFFFF;
            const unsigned m = __ballot_sync(0xFFFFFFFFu, v < w0);
            const int n = __popc(m);          // prefix count (monotone row)
            const int nlo = (n > 0) ? lo + (n - 1) * step + 1 : lo;
            const int nhi = (n < 32) ? min(hi, lo + n * step + 1) : hi;
            lo = nlo; hi = nhi;
        }
        if (c == 0) sm[0] = lo;
    }
    __syncthreads();

    // --- 2) cooperative window scan for starts of words w0+1..w0+8 ---
    {
        int bt = sm[0];
        for (;;) {
            if (c == 0) s_done = 0;
            __syncthreads();
            const int t = bt + c;
            const int w = (t <= S_DIM - 2) ? __ldg(row + t) : 0x7FFFFFFF;
            int wp = __shfl_up_sync(0xFFFFFFFFu, w, 1);
            if ((c & 31) == 0) {
                wp = (t >= 1 && t <= S_DIM - 1) ? __ldg(row + t - 1)
                                                : 0x7FFFFFFF;
            }
            if (w > w0 + W_PB) {
                s_done = 1;                   // all writers store 1: race OK
            } else if (w > w0 && wp != w) {
                sm[w - w0] = t;               // unique writer per boundary
            }
            __syncthreads();
            if (s_done) break;
            bt += NTHR;
        }
    }
    // sm[] is monotone: found boundaries increase; unfound tail = S-1.

    const int t0   = sm[0];
    const int tEnd = sm[W_PB];
    const int last = tEnd - 1;                // last in-range token index

    const char* __restrict__ base =
        hs + (size_t)b * S_DIM * ROW_BYTES + c * 16;
    char* __restrict__ ob =
        out + ((size_t)b * NUM_WORDS + w0) * ROW_BYTES + c * 16;

    // Running prefetch pointer (never dereferenced when out of range).
    const char* pf = base + (long)t0 * ROW_BYTES;

    // Prologue: fill all stages; out-of-range -> src-size 0 (zero-fill).
#pragma unroll
    for (int j = 0; j < STAGES; ++j) {
        const bool ok = (t0 + j) <= last;
        const char* src = ok ? pf : base;
        const int sz = ok ? 16 : 0;
        unsigned int dst = (unsigned int)__cvta_generic_to_shared(&buf[j][c]);
        asm volatile("cp.async.cg.shared.global [%0], [%1], 16, %2;"
                     :: "r"(dst), "l"(src), "r"(sz) : "memory");
        asm volatile("cp.async.commit_group;" ::: "memory");
        pf += ROW_BYTES;
    }

    int t = t0;
    int ring = 0;
#pragma unroll 1
    for (int i = 0; i < W_PB; ++i) {
        const int e   = sm[i + 1];
        const int cnt = e - t;

        float4 acc = make_float4(0.f, 0.f, 0.f, 0.f);
#pragma unroll 1
        while (t < e) {
            // Oldest outstanding group (stage `ring`) is complete.
            asm volatile("cp.async.wait_group %0;" :: "n"(STAGES - 1)
                         : "memory");
            float4 v = buf[ring][c];
            acc.x += v.x; acc.y += v.y; acc.z += v.z; acc.w += v.w;
            // Refill this stage with token t+STAGES (zero-fill past end).
            const bool ok = (t + STAGES) <= last;
            const char* src = ok ? pf : base;
            const int sz = ok ? 16 : 0;
            unsigned int dst =
                (unsigned int)__cvta_generic_to_shared(&buf[ring][c]);
            asm volatile("cp.async.cg.shared.global [%0], [%1], 16, %2;"
                         :: "r"(dst), "l"(src), "r"(sz) : "memory");
            asm volatile("cp.async.commit_group;" ::: "memory");
            pf += ROW_BYTES;
            ++t;
            ring = (ring + 1) & (STAGES - 1);
        }

        const float inv = (cnt > 0) ? (1.0f / (float)cnt) : 0.0f;
        float4 r;
        r.x = acc.x * inv; r.y = acc.y * inv;
        r.z = acc.z * inv; r.w = acc.w * inv;
        __stcs((float4*)(ob + (long)i * ROW_BYTES), r);
    }
}

extern "C" void kernel_launch(void* const* d_in, const int* in_sizes, int n_in,
                              void* d_out, int out_size)
{
    const char* hs  = (const char*)d_in[0];   // hidden_states [B,S,H] f32
    const int*  wid = (const int*)d_in[1];    // word_ids [B,S] i32
    char*       out = (char*)d_out;           // [B, NUM_WORDS, H] f32

    dim3 grid(NUM_WORDS / W_PB, B_DIM);
    seg_mean_fused_kernel<<<grid, NTHR>>>(hs, wid, out);
}